// round 1
// baseline (speedup 1.0000x reference)
#include <cuda_runtime.h>

#define B_   32
#define D_   64
#define T_   4096
#define N_   (B_ * T_)        // 131072 points
#define K_   1024
#define NDT  (B_ * D_ * T_)   // 8388608 z_q elements

#define KT   128              // codes per smem tile
#define TPB  256              // threads per block (assign)

__device__ float g_counts[K_];
__device__ float g_embed_sum[K_ * D_];
__device__ float g_e2[K_];
__device__ float g_new_embedding[K_ * D_];
__device__ int   g_indices[N_];
__device__ float g_loss;

// ---------------------------------------------------------------------------
// K0: zero the per-launch accumulators (graph is replayed, so must re-zero)
// ---------------------------------------------------------------------------
__global__ void zero_kernel() {
    int i = blockIdx.x * blockDim.x + threadIdx.x;
    if (i < K_ * D_) g_embed_sum[i] = 0.0f;
    if (i < K_)      g_counts[i]    = 0.0f;
    if (i == 0)      g_loss         = 0.0f;
}

// ---------------------------------------------------------------------------
// K1: precompute ||e_k||^2
// ---------------------------------------------------------------------------
__global__ void e2_kernel(const float* __restrict__ emb) {
    int k = blockIdx.x * blockDim.x + threadIdx.x;
    if (k >= K_) return;
    const float4* e = reinterpret_cast<const float4*>(emb + (size_t)k * D_);
    float s = 0.0f;
#pragma unroll
    for (int j = 0; j < D_ / 4; j++) {
        float4 v = e[j];
        s += v.x * v.x + v.y * v.y + v.z * v.z + v.w * v.w;
    }
    g_e2[k] = s;
}

// ---------------------------------------------------------------------------
// K2: assignment (argmin over codes) + fused segment-sum atomics.
// Each thread owns 2 points; embedding tiles staged through smem (broadcast
// LDS.128 reads). score = ||e||^2 - 2 z.e  (z^2 term is constant per row).
// ---------------------------------------------------------------------------
__global__ void __launch_bounds__(TPB)
assign_kernel(const float* __restrict__ z, const float* __restrict__ emb) {
    __shared__ float4 se[KT * (D_ / 4)];   // 128 codes * 64 f32 = 32 KB
    __shared__ float  se2[KT];

    const int n0 = blockIdx.x * (TPB * 2) + threadIdx.x;
    const int n1 = n0 + TPB;

    // Load both points' 64-dim vectors into registers.
    float z0[D_], z1[D_];
    {
        const int b0 = n0 / T_, t0 = n0 % T_;
        const int b1 = n1 / T_, t1 = n1 % T_;
        const float* p0 = z + (size_t)b0 * D_ * T_ + t0;
        const float* p1 = z + (size_t)b1 * D_ * T_ + t1;
#pragma unroll
        for (int d = 0; d < D_; d++) {
            z0[d] = p0[(size_t)d * T_];
            z1[d] = p1[(size_t)d * T_];
        }
    }

    float best0 = 3.4e38f, best1 = 3.4e38f;
    int   bi0 = 0, bi1 = 0;

    for (int k0 = 0; k0 < K_; k0 += KT) {
        __syncthreads();
        // Cooperative tile load: fully coalesced float4 stream.
        const float4* ge = reinterpret_cast<const float4*>(emb + (size_t)k0 * D_);
#pragma unroll
        for (int i = 0; i < (KT * (D_ / 4)) / TPB; i++)
            se[threadIdx.x + i * TPB] = ge[threadIdx.x + i * TPB];
        if (threadIdx.x < KT) se2[threadIdx.x] = g_e2[k0 + threadIdx.x];
        __syncthreads();

        for (int kk = 0; kk < KT; kk++) {
            // 4 independent FMA chains: (point0/point1) x (low/high halves of D)
            float d0a = 0.0f, d0b = 0.0f, d1a = 0.0f, d1b = 0.0f;
#pragma unroll
            for (int j = 0; j < 8; j++) {
                float4 e = se[kk * (D_ / 4) + j];
                d0a = fmaf(e.x, z0[4 * j + 0], d0a);
                d0a = fmaf(e.y, z0[4 * j + 1], d0a);
                d0a = fmaf(e.z, z0[4 * j + 2], d0a);
                d0a = fmaf(e.w, z0[4 * j + 3], d0a);
                d1a = fmaf(e.x, z1[4 * j + 0], d1a);
                d1a = fmaf(e.y, z1[4 * j + 1], d1a);
                d1a = fmaf(e.z, z1[4 * j + 2], d1a);
                d1a = fmaf(e.w, z1[4 * j + 3], d1a);
            }
#pragma unroll
            for (int j = 8; j < 16; j++) {
                float4 e = se[kk * (D_ / 4) + j];
                d0b = fmaf(e.x, z0[4 * j + 0], d0b);
                d0b = fmaf(e.y, z0[4 * j + 1], d0b);
                d0b = fmaf(e.z, z0[4 * j + 2], d0b);
                d0b = fmaf(e.w, z0[4 * j + 3], d0b);
                d1b = fmaf(e.x, z1[4 * j + 0], d1b);
                d1b = fmaf(e.y, z1[4 * j + 1], d1b);
                d1b = fmaf(e.z, z1[4 * j + 2], d1b);
                d1b = fmaf(e.w, z1[4 * j + 3], d1b);
            }
            const float e2 = se2[kk];
            const float s0 = e2 - 2.0f * (d0a + d0b);
            const float s1 = e2 - 2.0f * (d1a + d1b);
            const int k = k0 + kk;
            if (s0 < best0) { best0 = s0; bi0 = k; }   // strict < keeps first min (jnp.argmin)
            if (s1 < best1) { best1 = s1; bi1 = k; }
        }
    }

    g_indices[n0] = bi0;
    g_indices[n1] = bi1;
    atomicAdd(&g_counts[bi0], 1.0f);
    atomicAdd(&g_counts[bi1], 1.0f);
#pragma unroll
    for (int d = 0; d < D_; d++) {
        atomicAdd(&g_embed_sum[bi0 * D_ + d], z0[d]);
        atomicAdd(&g_embed_sum[bi1 * D_ + d], z1[d]);
    }
}

// ---------------------------------------------------------------------------
// K3: EMA update + Laplace smoothing + new embedding. One block of 1024
// threads (needs the block-wide sum n of new_cluster_size).
// ---------------------------------------------------------------------------
__global__ void update_kernel(const float* __restrict__ cs,
                              const float* __restrict__ ea) {
    __shared__ float red[32];
    __shared__ float s_n;
    const int k = threadIdx.x;   // 0..1023

    float ncs = cs[k] * 0.99f + 0.01f * g_counts[k];

    // block reduce sum(ncs)
    float v = ncs;
#pragma unroll
    for (int o = 16; o; o >>= 1) v += __shfl_xor_sync(0xFFFFFFFFu, v, o);
    if ((k & 31) == 0) red[k >> 5] = v;
    __syncthreads();
    if (k == 0) {
        float t = 0.0f;
#pragma unroll
        for (int i = 0; i < 32; i++) t += red[i];
        s_n = t;
    }
    __syncthreads();
    const float n = s_n;

    const float smoothed = (ncs + 1e-5f) / (n + (float)K_ * 1e-5f) * n;
    const float inv = 1.0f / smoothed;

    const float4* a4 = reinterpret_cast<const float4*>(ea + (size_t)k * D_);
    const float4* s4 = reinterpret_cast<const float4*>(g_embed_sum + (size_t)k * D_);
    float4*       o4 = reinterpret_cast<float4*>(g_new_embedding + (size_t)k * D_);
#pragma unroll
    for (int j = 0; j < D_ / 4; j++) {
        float4 a = a4[j];
        float4 s = s4[j];
        float4 r;
        r.x = (a.x * 0.99f + 0.01f * s.x) * inv;
        r.y = (a.y * 0.99f + 0.01f * s.y) * inv;
        r.z = (a.z * 0.99f + 0.01f * s.z) * inv;
        r.w = (a.w * 0.99f + 0.01f * s.w) * inv;
        o4[j] = r;
    }
}

// ---------------------------------------------------------------------------
// K4: gather z_q with straight-through formula, write z_q + indices,
// accumulate loss numerator.
// ---------------------------------------------------------------------------
__global__ void __launch_bounds__(256)
finalize_kernel(const float* __restrict__ z, float* __restrict__ out,
                int out_size) {
    const int n = blockIdx.x * blockDim.x + threadIdx.x;   // 0..N_-1
    const int idx = g_indices[n];
    const int b = n / T_, t = n % T_;
    const float* zp = z   + (size_t)b * D_ * T_ + t;
    float*       op = out + (size_t)b * D_ * T_ + t;
    const float4* e4 = reinterpret_cast<const float4*>(g_new_embedding + (size_t)idx * D_);

    float lacc = 0.0f;
#pragma unroll
    for (int j = 0; j < D_ / 4; j++) {
        float4 e = e4[j];
#pragma unroll
        for (int c = 0; c < 4; c++) {
            const int d = 4 * j + c;
            const float q  = (c == 0) ? e.x : (c == 1) ? e.y : (c == 2) ? e.z : e.w;
            const float zv = zp[(size_t)d * T_];
            const float df = zv - q;
            lacc = fmaf(df, df, lacc);
            // straight-through: z + stop_grad(q - z), reproduce fp op order
            op[(size_t)d * T_] = zv + (q - zv);
        }
    }

    if (NDT + 1 + n < out_size) out[NDT + 1 + n] = (float)idx;

    // loss reduction: warp shuffle -> smem -> one atomic per block
#pragma unroll
    for (int o = 16; o; o >>= 1) lacc += __shfl_xor_sync(0xFFFFFFFFu, lacc, o);
    __shared__ float sred[8];
    if ((threadIdx.x & 31) == 0) sred[threadIdx.x >> 5] = lacc;
    __syncthreads();
    if (threadIdx.x == 0) {
        float s = 0.0f;
#pragma unroll
        for (int i = 0; i < 8; i++) s += sred[i];
        atomicAdd(&g_loss, s);
    }
}

__global__ void loss_kernel(float* __restrict__ out, int out_size) {
    if (out_size > NDT)
        out[NDT] = 0.25f * g_loss / (float)((size_t)N_ * D_);
}

// ---------------------------------------------------------------------------
extern "C" void kernel_launch(void* const* d_in, const int* in_sizes, int n_in,
                              void* d_out, int out_size) {
    const float* z   = (const float*)d_in[0];   // [B, D, T]
    const float* emb = (const float*)d_in[1];   // [K, D]
    const float* cs  = (const float*)d_in[2];   // [K]
    const float* ea  = (const float*)d_in[3];   // [K, D]
    float* out = (float*)d_out;

    zero_kernel<<<(K_ * D_ + 255) / 256, 256>>>();
    e2_kernel<<<(K_ + 255) / 256, 256>>>(emb);
    assign_kernel<<<N_ / (TPB * 2), TPB>>>(z, emb);
    update_kernel<<<1, K_>>>(cs, ea);
    finalize_kernel<<<N_ / 256, 256>>>(z, out, out_size);
    loss_kernel<<<1, 1>>>(out, out_size);
}

// round 4
// speedup vs baseline: 1.1078x; 1.1078x over previous
#include <cuda_runtime.h>

#define B_   32
#define D_   64
#define T_   4096
#define N_   (B_ * T_)        // 131072 points
#define K_   1024
#define NDT  (B_ * D_ * T_)   // 8388608 z_q elements

#define KT   128              // codes per smem tile
#define TPB  256              // threads per block (assign)

typedef unsigned long long ull;

__device__ float g_counts[K_];
__device__ float g_embed_sum[K_ * D_];
__device__ float g_e2[K_];
__device__ float g_new_embedding[K_ * D_];
__device__ int   g_indices[N_];
__device__ float g_loss;
__device__ float g_n;

// ---- packed f32x2 helpers (Blackwell FFMA2 path; PTX-only) -----------------
__device__ __forceinline__ void fma2(ull& d, ull a, ull b) {
    asm("fma.rn.f32x2 %0, %1, %2, %3;" : "=l"(d) : "l"(a), "l"(b), "l"(d));
}
__device__ __forceinline__ ull add2(ull a, ull b) {
    ull r; asm("add.rn.f32x2 %0, %1, %2;" : "=l"(r) : "l"(a), "l"(b)); return r;
}
__device__ __forceinline__ ull pack2(float lo, float hi) {
    ull r; asm("mov.b64 %0, {%1, %2};" : "=l"(r) : "f"(lo), "f"(hi)); return r;
}
__device__ __forceinline__ float hsum2(ull p) {
    float lo, hi; asm("mov.b64 {%0, %1}, %2;" : "=f"(lo), "=f"(hi) : "l"(p));
    return lo + hi;
}

// ---------------------------------------------------------------------------
// K0: zero the per-launch accumulators (graph is replayed, so must re-zero)
// ---------------------------------------------------------------------------
__global__ void zero_kernel() {
    int i = blockIdx.x * blockDim.x + threadIdx.x;
    if (i < K_ * D_) g_embed_sum[i] = 0.0f;
    if (i < K_)      g_counts[i]    = 0.0f;
    if (i == 0)      g_loss         = 0.0f;
}

// ---------------------------------------------------------------------------
// K1: precompute ||e_k||^2
// ---------------------------------------------------------------------------
__global__ void e2_kernel(const float* __restrict__ emb) {
    int k = blockIdx.x * blockDim.x + threadIdx.x;
    if (k >= K_) return;
    const float4* e = reinterpret_cast<const float4*>(emb + (size_t)k * D_);
    float s = 0.0f;
#pragma unroll
    for (int j = 0; j < D_ / 4; j++) {
        float4 v = e[j];
        s += v.x * v.x + v.y * v.y + v.z * v.z + v.w * v.w;
    }
    g_e2[k] = s;
}

// ---------------------------------------------------------------------------
// K2: assignment via packed FFMA2. Each thread owns 2 points, z packed as
// f32x2 along D in registers; embedding tiles staged through smem and read
// as 64-bit packed lanes (LDS.128 broadcast). score = ||e||^2 - 2 z.e.
// ---------------------------------------------------------------------------
__global__ void __launch_bounds__(TPB)
assign_kernel(const float* __restrict__ z, const float* __restrict__ emb) {
    __shared__ float se[KT * D_];   // 128 codes * 64 f32 = 32 KB
    __shared__ float se2[KT];

    const int n0 = blockIdx.x * (TPB * 2) + threadIdx.x;
    const int n1 = n0 + TPB;

    // Load both points' 64-dim vectors, packed in D-pairs.
    ull z0p[D_ / 2], z1p[D_ / 2];
    {
        const int b0 = n0 / T_, t0 = n0 % T_;
        const int b1 = n1 / T_, t1 = n1 % T_;
        const float* p0 = z + (size_t)b0 * D_ * T_ + t0;
        const float* p1 = z + (size_t)b1 * D_ * T_ + t1;
#pragma unroll
        for (int j = 0; j < D_ / 2; j++) {
            z0p[j] = pack2(p0[(size_t)(2 * j) * T_], p0[(size_t)(2 * j + 1) * T_]);
            z1p[j] = pack2(p1[(size_t)(2 * j) * T_], p1[(size_t)(2 * j + 1) * T_]);
        }
    }

    float best0 = 3.4e38f, best1 = 3.4e38f;
    int   bi0 = 0, bi1 = 0;

    for (int k0 = 0; k0 < K_; k0 += KT) {
        __syncthreads();
        // Cooperative tile load: fully coalesced float4 stream.
        const float4* ge = reinterpret_cast<const float4*>(emb + (size_t)k0 * D_);
        float4* se4 = reinterpret_cast<float4*>(se);
#pragma unroll
        for (int i = 0; i < (KT * (D_ / 4)) / TPB; i++)
            se4[threadIdx.x + i * TPB] = ge[threadIdx.x + i * TPB];
        if (threadIdx.x < KT) se2[threadIdx.x] = g_e2[k0 + threadIdx.x];
        __syncthreads();

        const ulonglong2* seu = reinterpret_cast<const ulonglong2*>(se);
#pragma unroll 4
        for (int kk = 0; kk < KT; kk++) {
            // 2 independent FFMA2 chains per point (lat 4, rt 2 -> distance 4 ok)
            ull a0 = 0ull, a1 = 0ull, b0 = 0ull, b1 = 0ull;
#pragma unroll
            for (int j = 0; j < D_ / 4; j++) {          // 16 x LDS.128
                ulonglong2 e = seu[kk * (D_ / 4) + j];
                fma2(a0, e.x, z0p[2 * j + 0]);
                fma2(b0, e.x, z1p[2 * j + 0]);
                fma2(a1, e.y, z0p[2 * j + 1]);
                fma2(b1, e.y, z1p[2 * j + 1]);
            }
            const float e2 = se2[kk];
            const float s0 = fmaf(-2.0f, hsum2(add2(a0, a1)), e2);
            const float s1 = fmaf(-2.0f, hsum2(add2(b0, b1)), e2);
            const int k = k0 + kk;
            if (s0 < best0) { best0 = s0; bi0 = k; }   // strict < keeps first min
            if (s1 < best1) { best1 = s1; bi1 = k; }
        }
    }

    g_indices[n0] = bi0;
    g_indices[n1] = bi1;
    atomicAdd(&g_counts[bi0], 1.0f);
    atomicAdd(&g_counts[bi1], 1.0f);
#pragma unroll
    for (int j = 0; j < D_ / 2; j++) {
        float lo, hi;
        asm("mov.b64 {%0, %1}, %2;" : "=f"(lo), "=f"(hi) : "l"(z0p[j]));
        atomicAdd(&g_embed_sum[bi0 * D_ + 2 * j + 0], lo);
        atomicAdd(&g_embed_sum[bi0 * D_ + 2 * j + 1], hi);
        asm("mov.b64 {%0, %1}, %2;" : "=f"(lo), "=f"(hi) : "l"(z1p[j]));
        atomicAdd(&g_embed_sum[bi1 * D_ + 2 * j + 0], lo);
        atomicAdd(&g_embed_sum[bi1 * D_ + 2 * j + 1], hi);
    }
}

// ---------------------------------------------------------------------------
// K3a: n = sum(cluster_size*decay + (1-decay)*counts). One small block.
// ---------------------------------------------------------------------------
__global__ void sum_kernel(const float* __restrict__ cs) {
    __shared__ float red[32];
    const int k = threadIdx.x;   // 0..1023
    float v = cs[k] * 0.99f + 0.01f * g_counts[k];
#pragma unroll
    for (int o = 16; o; o >>= 1) v += __shfl_xor_sync(0xFFFFFFFFu, v, o);
    if ((k & 31) == 0) red[k >> 5] = v;
    __syncthreads();
    if (k == 0) {
        float t = 0.0f;
#pragma unroll
        for (int i = 0; i < 32; i++) t += red[i];
        g_n = t;
    }
}

// ---------------------------------------------------------------------------
// K3b: EMA update + Laplace smoothing + new embedding (parallel, many blocks)
// ---------------------------------------------------------------------------
__global__ void update_kernel(const float* __restrict__ cs,
                              const float* __restrict__ ea) {
    const int k = blockIdx.x * blockDim.x + threadIdx.x;   // 0..1023
    if (k >= K_) return;
    const float n = g_n;
    const float ncs = cs[k] * 0.99f + 0.01f * g_counts[k];
    const float smoothed = (ncs + 1e-5f) / (n + (float)K_ * 1e-5f) * n;
    const float inv = 1.0f / smoothed;

    const float4* a4 = reinterpret_cast<const float4*>(ea + (size_t)k * D_);
    const float4* s4 = reinterpret_cast<const float4*>(g_embed_sum + (size_t)k * D_);
    float4*       o4 = reinterpret_cast<float4*>(g_new_embedding + (size_t)k * D_);
#pragma unroll
    for (int j = 0; j < D_ / 4; j++) {
        float4 a = a4[j];
        float4 s = s4[j];
        float4 r;
        r.x = (a.x * 0.99f + 0.01f * s.x) * inv;
        r.y = (a.y * 0.99f + 0.01f * s.y) * inv;
        r.z = (a.z * 0.99f + 0.01f * s.z) * inv;
        r.w = (a.w * 0.99f + 0.01f * s.w) * inv;
        o4[j] = r;
    }
}

// ---------------------------------------------------------------------------
// K4: gather z_q with straight-through formula, write z_q + indices,
// accumulate loss numerator.
// ---------------------------------------------------------------------------
__global__ void __launch_bounds__(256)
finalize_kernel(const float* __restrict__ z, float* __restrict__ out,
                int out_size) {
    const int n = blockIdx.x * blockDim.x + threadIdx.x;   // 0..N_-1
    const int idx = g_indices[n];
    const int b = n / T_, t = n % T_;
    const float* zp = z   + (size_t)b * D_ * T_ + t;
    float*       op = out + (size_t)b * D_ * T_ + t;
    const float4* e4 = reinterpret_cast<const float4*>(g_new_embedding + (size_t)idx * D_);

    float lacc = 0.0f;
#pragma unroll
    for (int j = 0; j < D_ / 4; j++) {
        float4 e = e4[j];
#pragma unroll
        for (int c = 0; c < 4; c++) {
            const int d = 4 * j + c;
            const float q  = (c == 0) ? e.x : (c == 1) ? e.y : (c == 2) ? e.z : e.w;
            const float zv = zp[(size_t)d * T_];
            const float df = zv - q;
            lacc = fmaf(df, df, lacc);
            op[(size_t)d * T_] = zv + (q - zv);   // straight-through fp order
        }
    }

    if (NDT + 1 + n < out_size) out[NDT + 1 + n] = (float)idx;

#pragma unroll
    for (int o = 16; o; o >>= 1) lacc += __shfl_xor_sync(0xFFFFFFFFu, lacc, o);
    __shared__ float sred[8];
    if ((threadIdx.x & 31) == 0) sred[threadIdx.x >> 5] = lacc;
    __syncthreads();
    if (threadIdx.x == 0) {
        float s = 0.0f;
#pragma unroll
        for (int i = 0; i < 8; i++) s += sred[i];
        atomicAdd(&g_loss, s);
    }
}

__global__ void loss_kernel(float* __restrict__ out, int out_size) {
    if (out_size > NDT)
        out[NDT] = 0.25f * g_loss / (float)((size_t)N_ * D_);
}

// ---------------------------------------------------------------------------
extern "C" void kernel_launch(void* const* d_in, const int* in_sizes, int n_in,
                              void* d_out, int out_size) {
    const float* z   = (const float*)d_in[0];   // [B, D, T]
    const float* emb = (const float*)d_in[1];   // [K, D]
    const float* cs  = (const float*)d_in[2];   // [K]
    const float* ea  = (const float*)d_in[3];   // [K, D]
    float* out = (float*)d_out;

    zero_kernel<<<(K_ * D_ + 255) / 256, 256>>>();
    e2_kernel<<<(K_ + 255) / 256, 256>>>(emb);
    assign_kernel<<<N_ / (TPB * 2), TPB>>>(z, emb);
    sum_kernel<<<1, K_>>>(cs);
    update_kernel<<<K_ / 128, 128>>>(cs, ea);
    finalize_kernel<<<N_ / 256, 256>>>(z, out, out_size);
    loss_kernel<<<1, 1>>>(out, out_size);
}

// round 6
// speedup vs baseline: 1.9430x; 1.7539x over previous
#include <cuda_runtime.h>
#include <cstdint>

#define B_   32
#define D_   64
#define T_   4096
#define N_   (B_ * T_)        // 131072 points
#define K_   1024
#define NDT  (B_ * D_ * T_)   // 8388608 z_q elements

#define MTILE   128           // points per CTA
#define NCHUNK  128           // codes per smem chunk
#define NCHUNKS (K_ / NCHUNK) // 8
#define TPB     256
#define BSTRIDE 68            // padded row stride (floats) for B images

// dynamic smem (floats): he2[1024] | bhi[128*68] | blo[128*68]
#define SMF_HE2  0
#define SMF_BHI  1024
#define SMF_BLO  (1024 + NCHUNK * BSTRIDE)
#define SMF_TOT  (1024 + 2 * NCHUNK * BSTRIDE)   // 18432 floats = 73728 B

__device__ float g_counts[K_];
__device__ float g_embed_sum[K_ * D_];
__device__ float g_he2[K_];                   // 0.5*||e||^2
__device__ float g_new_embedding[K_ * D_];
__device__ int   g_indices[N_];
__device__ float g_loss;
__device__ float g_n;

__device__ __forceinline__ uint32_t f2tf32(float v) {
    uint32_t r; asm("cvt.rna.tf32.f32 %0, %1;" : "=r"(r) : "f"(v)); return r;
}

__device__ __forceinline__ void mma_tf32(float& c0, float& c1, float& c2, float& c3,
                                         uint32_t a0, uint32_t a1, uint32_t a2, uint32_t a3,
                                         uint32_t b0, uint32_t b1) {
    asm volatile("mma.sync.aligned.m16n8k8.row.col.f32.tf32.tf32.f32 "
                 "{%0,%1,%2,%3}, {%4,%5,%6,%7}, {%8,%9}, {%0,%1,%2,%3};"
                 : "+f"(c0), "+f"(c1), "+f"(c2), "+f"(c3)
                 : "r"(a0), "r"(a1), "r"(a2), "r"(a3), "r"(b0), "r"(b1));
}

// ======================= small kernels =======================
__global__ void zero_kernel() {
    int i = blockIdx.x * blockDim.x + threadIdx.x;
    if (i < K_ * D_) g_embed_sum[i] = 0.0f;
    if (i < K_)      g_counts[i]    = 0.0f;
    if (i == 0)      g_loss         = 0.0f;
}

__global__ void nop_kernel() {}

__global__ void prep_kernel(const float* __restrict__ emb) {
    int k = blockIdx.x * blockDim.x + threadIdx.x;
    if (k >= K_) return;
    const float4* e = reinterpret_cast<const float4*>(emb + (size_t)k * D_);
    float s = 0.0f;
#pragma unroll
    for (int j = 0; j < D_ / 4; j++) {
        float4 v = e[j];
        s += v.x * v.x + v.y * v.y + v.z * v.z + v.w * v.w;
    }
    g_he2[k] = 0.5f * s;
}

// ---------------------------------------------------------------------------
// assign: warp-level HMMA tf32 3-split GEMM + fused argmin + segment atomics.
// score(n) = 0.5||e_n||^2 - z.e_n  (equiv-argmin of squared distance)
// ---------------------------------------------------------------------------
__global__ void __launch_bounds__(TPB, 2)
assign_kernel(const float* __restrict__ z, const float* __restrict__ emb) {
    extern __shared__ float sm[];
    float* he2s = sm + SMF_HE2;
    float* bhi  = sm + SMF_BHI;
    float* blo  = sm + SMF_BLO;

    const int tid = threadIdx.x;
    const int w   = tid >> 5;
    const int l   = tid & 31;
    const int g   = l >> 2;     // group (row within quad structure)
    const int q   = l & 3;      // thread-in-group (col)

    const int bq = blockIdx.x >> 5;          // batch
    const int t0 = (blockIdx.x & 31) << 7;   // tile start within T
    const float* zb = z + (size_t)bq * D_ * T_ + t0;

    // he2 -> smem
#pragma unroll
    for (int i = 0; i < K_ / TPB; i++) he2s[tid + i * TPB] = g_he2[tid + i * TPB];

    // --- A fragments (z tile rows 16w..16w+16), hi/lo tf32, held in regs ---
    // a0:(r0,q) a1:(r1,q) a2:(r0,q+4) a3:(r1,q+4) per 8-wide k-step
    const int r0 = 16 * w + g;
    const int r1 = r0 + 8;
    uint32_t Ahi[32], Alo[32];
#pragma unroll
    for (int ks = 0; ks < 8; ks++) {
#pragma unroll
        for (int p = 0; p < 4; p++) {
            const int r = (p & 1) ? r1 : r0;
            const int c = ks * 8 + q + ((p & 2) ? 4 : 0);   // d index
            const float v  = zb[(size_t)c * T_ + r];
            const uint32_t hb = f2tf32(v);
            Ahi[ks * 4 + p] = hb;
            Alo[ks * 4 + p] = f2tf32(v - __uint_as_float(hb));
        }
    }

    // trackers: rows r0 and r1, over this lane's columns
    float best0 = 3.4e38f, best1 = 3.4e38f;
    int   bi0 = 0, bi1 = 0;

    for (int ch = 0; ch < NCHUNKS; ch++) {
        __syncthreads();
        // cooperative load + tf32 hi/lo split of 128-code chunk
        const float4* ge4 = reinterpret_cast<const float4*>(emb) + ch * (NCHUNK * D_ / 4);
#pragma unroll
        for (int i = 0; i < (NCHUNK * D_ / 4) / TPB; i++) {
            const int f  = tid + i * TPB;          // float4 index in chunk
            const int nl = f >> 4;                 // local code
            const int k  = (f & 15) * 4;
            float4 v = ge4[f];
            const float vs[4] = {v.x, v.y, v.z, v.w};
#pragma unroll
            for (int c = 0; c < 4; c++) {
                const uint32_t hb = f2tf32(vs[c]);
                bhi[nl * BSTRIDE + k + c] = __uint_as_float(hb);
                blo[nl * BSTRIDE + k + c] = __uint_as_float(f2tf32(vs[c] - __uint_as_float(hb)));
            }
        }
        __syncthreads();

#pragma unroll 2
        for (int tile = 0; tile < NCHUNK / 8; tile++) {
            const int nb = tile * 8;                   // local code base
            const int cb = ch * NCHUNK + nb;           // global code base
            float c0 = 0.0f, c1 = 0.0f, c2 = 0.0f, c3 = 0.0f;
            const int brow = (nb + g) * BSTRIDE;
#pragma unroll
            for (int ks = 0; ks < 8; ks++) {
                // b0:(k=q, n=g) b1:(k=q+4, n=g)
                const uint32_t bh0 = __float_as_uint(bhi[brow + ks * 8 + q]);
                const uint32_t bh1 = __float_as_uint(bhi[brow + ks * 8 + q + 4]);
                const uint32_t bl0 = __float_as_uint(blo[brow + ks * 8 + q]);
                const uint32_t bl1 = __float_as_uint(blo[brow + ks * 8 + q + 4]);
                mma_tf32(c0, c1, c2, c3, Ahi[4*ks], Ahi[4*ks+1], Ahi[4*ks+2], Ahi[4*ks+3], bh0, bh1);
                mma_tf32(c0, c1, c2, c3, Ahi[4*ks], Ahi[4*ks+1], Ahi[4*ks+2], Ahi[4*ks+3], bl0, bl1);
                mma_tf32(c0, c1, c2, c3, Alo[4*ks], Alo[4*ks+1], Alo[4*ks+2], Alo[4*ks+3], bh0, bh1);
            }
            // c0:(r0, 2q) c1:(r0, 2q+1) c2:(r1, 2q) c3:(r1, 2q+1)
            const float h0 = he2s[cb + 2 * q];
            const float h1 = he2s[cb + 2 * q + 1];
            const float s00 = h0 - c0, s01 = h1 - c1;
            const float s10 = h0 - c2, s11 = h1 - c3;
            const int n0 = cb + 2 * q, n1 = n0 + 1;
            if (s00 < best0) { best0 = s00; bi0 = n0; }
            if (s01 < best0) { best0 = s01; bi0 = n1; }
            if (s10 < best1) { best1 = s10; bi1 = n0; }
            if (s11 < best1) { best1 = s11; bi1 = n1; }
        }
    }

    // cross-quad reduce (lanes 4g..4g+3 hold rows r0,r1); lower idx wins ties
#pragma unroll
    for (int o = 1; o <= 2; o <<= 1) {
        float ob = __shfl_xor_sync(0xFFFFFFFFu, best0, o);
        int   oi = __shfl_xor_sync(0xFFFFFFFFu, bi0,   o);
        if (ob < best0 || (ob == best0 && oi < bi0)) { best0 = ob; bi0 = oi; }
        ob = __shfl_xor_sync(0xFFFFFFFFu, best1, o);
        oi = __shfl_xor_sync(0xFFFFFFFFu, bi1,   o);
        if (ob < best1 || (ob == best1 && oi < bi1)) { best1 = ob; bi1 = oi; }
    }

    __syncthreads();                      // he2s reads done; reuse sm[0..128)
    int* ridx = reinterpret_cast<int*>(sm);
    if (q == 0) { ridx[r0] = bi0; ridx[r1] = bi1; }
    __syncthreads();

    // outputs: 2 threads per point (32 dims each)
    const int m    = tid & 127;
    const int half = tid >> 7;
    const int bi   = ridx[m];
    if (half == 0) {
        g_indices[bq * T_ + t0 + m] = bi;
        atomicAdd(&g_counts[bi], 1.0f);
    }
#pragma unroll
    for (int d = 32 * half; d < 32 * half + 32; d++)
        atomicAdd(&g_embed_sum[bi * D_ + d], zb[(size_t)d * T_ + m]);
}

// ---------------------------------------------------------------------------
__global__ void sum_kernel(const float* __restrict__ cs) {
    __shared__ float red[32];
    const int k = threadIdx.x;
    float v = cs[k] * 0.99f + 0.01f * g_counts[k];
#pragma unroll
    for (int o = 16; o; o >>= 1) v += __shfl_xor_sync(0xFFFFFFFFu, v, o);
    if ((k & 31) == 0) red[k >> 5] = v;
    __syncthreads();
    if (k == 0) {
        float t = 0.0f;
#pragma unroll
        for (int i = 0; i < 32; i++) t += red[i];
        g_n = t;
    }
}

__global__ void update_kernel(const float* __restrict__ cs,
                              const float* __restrict__ ea) {
    const int k = blockIdx.x * blockDim.x + threadIdx.x;
    if (k >= K_) return;
    const float n = g_n;
    const float ncs = cs[k] * 0.99f + 0.01f * g_counts[k];
    const float smoothed = (ncs + 1e-5f) / (n + (float)K_ * 1e-5f) * n;
    const float inv = 1.0f / smoothed;
    const float4* a4 = reinterpret_cast<const float4*>(ea + (size_t)k * D_);
    const float4* s4 = reinterpret_cast<const float4*>(g_embed_sum + (size_t)k * D_);
    float4*       o4 = reinterpret_cast<float4*>(g_new_embedding + (size_t)k * D_);
#pragma unroll
    for (int j = 0; j < D_ / 4; j++) {
        float4 a = a4[j];
        float4 s = s4[j];
        float4 r;
        r.x = (a.x * 0.99f + 0.01f * s.x) * inv;
        r.y = (a.y * 0.99f + 0.01f * s.y) * inv;
        r.z = (a.z * 0.99f + 0.01f * s.z) * inv;
        r.w = (a.w * 0.99f + 0.01f * s.w) * inv;
        o4[j] = r;
    }
}

__global__ void __launch_bounds__(256)
finalize_kernel(const float* __restrict__ z, float* __restrict__ out, int out_size) {
    const int n = blockIdx.x * blockDim.x + threadIdx.x;
    const int idx = g_indices[n];
    const int b = n / T_, t = n % T_;
    const float* zp = z   + (size_t)b * D_ * T_ + t;
    float*       op = out + (size_t)b * D_ * T_ + t;
    const float4* e4 = reinterpret_cast<const float4*>(g_new_embedding + (size_t)idx * D_);

    float lacc = 0.0f;
#pragma unroll
    for (int j = 0; j < D_ / 4; j++) {
        float4 e = e4[j];
#pragma unroll
        for (int c = 0; c < 4; c++) {
            const int d = 4 * j + c;
            const float qv = (c == 0) ? e.x : (c == 1) ? e.y : (c == 2) ? e.z : e.w;
            const float zv = zp[(size_t)d * T_];
            const float df = zv - qv;
            lacc = fmaf(df, df, lacc);
            op[(size_t)d * T_] = zv + (qv - zv);   // straight-through fp order
        }
    }
    if (NDT + 1 + n < out_size) out[NDT + 1 + n] = (float)idx;

#pragma unroll
    for (int o = 16; o; o >>= 1) lacc += __shfl_xor_sync(0xFFFFFFFFu, lacc, o);
    __shared__ float sred[8];
    if ((threadIdx.x & 31) == 0) sred[threadIdx.x >> 5] = lacc;
    __syncthreads();
    if (threadIdx.x == 0) {
        float s = 0.0f;
#pragma unroll
        for (int i = 0; i < 8; i++) s += sred[i];
        atomicAdd(&g_loss, s);
    }
}

__global__ void loss_kernel(float* __restrict__ out, int out_size) {
    if (out_size > NDT)
        out[NDT] = 0.25f * g_loss / (float)((size_t)N_ * D_);
}

// ---------------------------------------------------------------------------
extern "C" void kernel_launch(void* const* d_in, const int* in_sizes, int n_in,
                              void* d_out, int out_size) {
    const float* z   = (const float*)d_in[0];   // [B, D, T]
    const float* emb = (const float*)d_in[1];   // [K, D]
    const float* cs  = (const float*)d_in[2];   // [K]
    const float* ea  = (const float*)d_in[3];   // [K, D]
    float* out = (float*)d_out;

    cudaFuncSetAttribute(assign_kernel, cudaFuncAttributeMaxDynamicSharedMemorySize,
                         SMF_TOT * (int)sizeof(float));

    zero_kernel<<<(K_ * D_ + 255) / 256, 256>>>();
    prep_kernel<<<K_ / 256, 256>>>(emb);
    // padding so assign is the 6th launch (ncu -s 5 -c 1 captures it)
    nop_kernel<<<1, 1>>>();
    nop_kernel<<<1, 1>>>();
    nop_kernel<<<1, 1>>>();
    assign_kernel<<<N_ / MTILE, TPB, SMF_TOT * sizeof(float)>>>(z, emb);
    sum_kernel<<<1, K_>>>(cs);
    update_kernel<<<K_ / 128, 128>>>(cs, ea);
    finalize_kernel<<<N_ / 256, 256>>>(z, out, out_size);
    loss_kernel<<<1, 1>>>(out, out_size);
}